// round 3
// baseline (speedup 1.0000x reference)
#include <cuda_runtime.h>
#include <math.h>

#define N 320
#define D 128
#define NMAT 3            // src0, src1, emb
#define RHO_C 10.0f
#define MARGIN_C 0.2f
#define TAU_C 1.3f
#define SEMIHARD_THRESH_C 0.01f
#define EPS_C 1e-12f

// ---------------- device scratch (no allocations allowed) ----------------
__device__ float g_norm[NMAT][N][D];     // normalized rows
__device__ float g_dist[NMAT][N][N];     // pairwise distances per matrix
__device__ float g_pw[N][N];             // pair weights from averaged source dists
__device__ float g_partden[400];         // per-block partial sums of pair_w
__device__ float g_partnum[N];           // per-i partial sums of pos*pair_w

// ---------------- kernel 1: row L2 normalization ----------------
// grid: 3*N blocks, 128 threads (one per feature)
__global__ void k_normalize(const float* __restrict__ src,
                            const float* __restrict__ emb) {
    int row = blockIdx.x;          // 0 .. 3*N-1
    int m = row / N;               // matrix id
    int r = row % N;
    const float* p = (m < 2) ? (src + ((size_t)m * N + r) * D) : (emb + (size_t)r * D);
    int t = threadIdx.x;
    float x = p[t];

    __shared__ float sred[128];
    sred[t] = x * x;
    __syncthreads();
    #pragma unroll
    for (int s = 64; s > 0; s >>= 1) {
        if (t < s) sred[t] += sred[t + s];
        __syncthreads();
    }
    float nrm = sqrtf(sred[0]);
    float rn = 1.0f / fmaxf(nrm, EPS_C);
    g_norm[m][r][t] = x * rn;
}

// ---------------- kernel 2: pairwise distances ----------------
// grid: (20, 20, 3), 256 threads; each block computes a 16x16 tile of d
__global__ void k_dist() {
    int m = blockIdx.z;
    int i0 = blockIdx.y * 16;
    int j0 = blockIdx.x * 16;
    __shared__ float Ai[16][D + 1];   // +1 pad: avoid bank conflicts
    __shared__ float Aj[16][D + 1];

    int t = threadIdx.x;
    for (int e = t; e < 16 * D; e += 256) {
        int r = e / D, c = e % D;
        Ai[r][c] = g_norm[m][i0 + r][c];
        Aj[r][c] = g_norm[m][j0 + r][c];
    }
    __syncthreads();

    int tx = t & 15, ty = t >> 4;
    float dot = 0.f, si = 0.f, sj = 0.f;
    #pragma unroll 8
    for (int c = 0; c < D; c++) {
        float a = Ai[ty][c];
        float b = Aj[tx][c];
        dot += a * b;
        si  += a * a;
        sj  += b * b;
    }
    float d2 = si + sj - 2.0f * dot;
    g_dist[m][i0 + ty][j0 + tx] = sqrtf(fmaxf(d2, 0.0f) + EPS_C);
}

// ---------------- kernel 3: pair weights + den partials ----------------
// grid: 400 blocks x 256 threads over N*N = 102400 elems
__global__ void k_pw() {
    int idx = blockIdx.x * 256 + threadIdx.x;
    const float* d0 = &g_dist[0][0][0];
    const float* d1 = &g_dist[1][0][0];
    float pw = 0.0f;
    if (idx < N * N) {
        float davg = 0.5f * (d0[idx] + d1[idx]);
        pw = 1.0f / (1.0f + expf(-RHO_C * (TAU_C - davg)));
        (&g_pw[0][0])[idx] = pw;
    }
    // block reduction (fixed order -> deterministic partials)
    float v = pw;
    #pragma unroll
    for (int o = 16; o > 0; o >>= 1) v += __shfl_down_sync(0xffffffffu, v, o);
    __shared__ float swp[8];
    int lane = threadIdx.x & 31, warp = threadIdx.x >> 5;
    if (lane == 0) swp[warp] = v;
    __syncthreads();
    if (warp == 0) {
        float w = (lane < 8) ? swp[lane] : 0.0f;
        #pragma unroll
        for (int o = 4; o > 0; o >>= 1) w += __shfl_down_sync(0xffffffffu, w, o);
        if (lane == 0) g_partden[blockIdx.x] = w;
    }
}

// ---------------- kernel 4: O(N^3) triplet pass ----------------
// grid: N blocks (one per i), N threads (one per j)
__global__ void __launch_bounds__(N) k_triplet() {
    int i = blockIdx.x;
    int j = threadIdx.x;

    __shared__ float sd[N];
    __shared__ float spw[N];
    sd[j]  = g_dist[2][i][j];
    spw[j] = g_pw[i][j];
    __syncthreads();

    float dij  = sd[j];
    float pwij = spw[j];

    float maxs = 0.0f;       // pos_semihard (products are >= 0)
    float minn = 1e30f;      // norm_l

    #pragma unroll 4
    for (int k = 0; k < N; k++) {
        float dk = sd[k];               // warp-uniform broadcast
        float bk = 1.0f - spw[k];       // warp-uniform broadcast
        // Match reference association: diff = d[i,k] - d[i,j];
        // tl = relu(MARGIN - diff). For k==j this gives tl == 0.2f EXACTLY
        // (semihard). Do NOT refactor to (MARGIN + dij) - dk.
        float diff = dk - dij;
        float tl = fmaxf(MARGIN_C - diff, 0.0f);
        float w  = pwij * bk;
        float vs = (tl > 0.0f && tl <= MARGIN_C) ? tl * w : 0.0f;
        maxs = fmaxf(maxs, vs);
        float vh = (tl > MARGIN_C) ? (tl - RHO_C * w) : tl;
        minn = fminf(minn, vh);
    }

    float pos_hard = (minn < 0.0f) ? (minn + RHO_C) : 0.0f;
    float pos = maxs + ((maxs <= SEMIHARD_THRESH_C) ? pos_hard : 0.0f);
    float contrib = pos * pwij;

    // deterministic block reduction of 320 values
    float v = contrib;
    #pragma unroll
    for (int o = 16; o > 0; o >>= 1) v += __shfl_down_sync(0xffffffffu, v, o);
    __shared__ float swp[10];
    int lane = j & 31, warp = j >> 5;
    if (lane == 0) swp[warp] = v;
    __syncthreads();
    if (warp == 0) {
        float w = (lane < 10) ? swp[lane] : 0.0f;
        #pragma unroll
        for (int o = 8; o > 0; o >>= 1) w += __shfl_down_sync(0xffffffffu, w, o);
        if (lane == 0) g_partnum[i] = w;
    }
}

// ---------------- kernel 5: final scalar ----------------
__global__ void k_final(float* __restrict__ out) {
    int t = threadIdx.x;   // 32 threads
    float num = 0.0f, den = 0.0f;
    for (int b = t; b < N; b += 32)   num += g_partnum[b];
    for (int b = t; b < 400; b += 32) den += g_partden[b];
    #pragma unroll
    for (int o = 16; o > 0; o >>= 1) {
        num += __shfl_down_sync(0xffffffffu, num, o);
        den += __shfl_down_sync(0xffffffffu, den, o);
    }
    if (t == 0) out[0] = (den > 0.0f) ? (num / fmaxf(den, EPS_C)) : 0.0f;
}

extern "C" void kernel_launch(void* const* d_in, const int* in_sizes, int n_in,
                              void* d_out, int out_size) {
    (void)n_in; (void)out_size;
    // metadata order: source_embeddings [2,320,128], embeddings [320,128]
    const float* src = (const float*)d_in[0];
    const float* emb = (const float*)d_in[1];
    // defensive: if sizes indicate swapped order, swap
    if (n_in >= 2 && in_sizes[0] == N * D && in_sizes[1] == 2 * N * D) {
        const float* tmp = src; src = emb; emb = tmp;
    }
    float* out = (float*)d_out;

    k_normalize<<<NMAT * N, 128>>>(src, emb);
    k_dist<<<dim3(N / 16, N / 16, NMAT), 256>>>();
    k_pw<<<400, 256>>>();
    k_triplet<<<N, N>>>();
    k_final<<<1, 32>>>(out);
}

// round 4
// speedup vs baseline: 1.3998x; 1.3998x over previous
#include <cuda_runtime.h>
#include <math.h>

#define N 320
#define D 128
#define NMAT 3            // src0, src1, emb
#define RHO_C 10.0f
#define MARGIN_C 0.2f
#define TAU_C 1.3f
#define SEMIHARD_THRESH_C 0.01f
#define EPS_C 1e-12f

// ---------------- device scratch (no allocations allowed) ----------------
__device__ float  g_norm[NMAT][N][D];   // normalized rows
__device__ float  g_sq[NMAT][N];        // per-row sum of squares of normalized row
__device__ float  g_pw[N][N];           // pair weights
__device__ float2 g_tk[N][N];           // (d_emb[i][k], 1 - pw[i][k])
__device__ float  g_partden[400];       // per-block partial sums of pair_w
__device__ float  g_partnum[N];         // per-i partial sums of pos*pair_w
__device__ unsigned int g_counter;      // last-block ticket for fused final

// ---------------- kernel 1: row L2 normalization (+ sq, + counter reset) ----
// grid: 3*N blocks, 128 threads (one per feature)
__global__ void k_normalize(const float* __restrict__ src,
                            const float* __restrict__ emb) {
    int row = blockIdx.x;          // 0 .. 3*N-1
    int m = row / N;
    int r = row % N;
    const float* p = (m < 2) ? (src + ((size_t)m * N + r) * D) : (emb + (size_t)r * D);
    int t = threadIdx.x;
    if (row == 0 && t == 0) g_counter = 0;   // reset ticket every launch (deterministic)
    float x = p[t];

    __shared__ float sred[128];
    sred[t] = x * x;
    __syncthreads();
    #pragma unroll
    for (int s = 64; s > 0; s >>= 1) {
        if (t < s) sred[t] += sred[t + s];
        __syncthreads();
    }
    float nrm = sqrtf(sred[0]);
    float rn = 1.0f / fmaxf(nrm, EPS_C);
    float a = x * rn;
    g_norm[m][r][t] = a;

    // sq of normalized row (same tree order every launch)
    __syncthreads();
    sred[t] = a * a;
    __syncthreads();
    #pragma unroll
    for (int s = 64; s > 0; s >>= 1) {
        if (t < s) sred[t] += sred[t + s];
        __syncthreads();
    }
    if (t == 0) g_sq[m][r] = sred[0];
}

// ---------------- kernel 2: fused distances + pair weights + den partials ---
// grid: (20, 20), 256 threads; each block owns a 16x16 (i,j) tile, loops m.
#define PADW 132   // 128 + 4 floats pad; keeps float4 alignment, tames conflicts
__global__ void __launch_bounds__(256) k_distpw() {
    int i0 = blockIdx.y * 16;
    int j0 = blockIdx.x * 16;
    __shared__ float Ai[16][PADW];
    __shared__ float Aj[16][PADW];

    int t  = threadIdx.x;
    int tx = t & 15, ty = t >> 4;
    int i = i0 + ty, j = j0 + tx;

    float dsum = 0.0f;
    float demb = 0.0f;

    #pragma unroll 1
    for (int m = 0; m < NMAT; m++) {
        __syncthreads();   // protect previous iteration's reads
        // vectorized tile load: 16 rows x 32 float4 per side, 2 per thread/side
        for (int e = t; e < 16 * 32; e += 256) {
            int r = e >> 5, c4 = e & 31;
            const float4* gi = (const float4*)&g_norm[m][i0 + r][0];
            const float4* gj = (const float4*)&g_norm[m][j0 + r][0];
            *(float4*)&Ai[r][c4 * 4] = gi[c4];
            *(float4*)&Aj[r][c4 * 4] = gj[c4];
        }
        __syncthreads();

        const float4* ai = (const float4*)&Ai[ty][0];
        const float4* aj = (const float4*)&Aj[tx][0];
        float d0 = 0.f, d1 = 0.f, d2a = 0.f, d3 = 0.f;
        #pragma unroll 8
        for (int c = 0; c < 32; c++) {
            float4 a = ai[c];
            float4 b = aj[c];
            d0 += a.x * b.x;
            d1 += a.y * b.y;
            d2a += a.z * b.z;
            d3 += a.w * b.w;
        }
        float dot = (d0 + d1) + (d2a + d3);
        float sqi = g_sq[m][i];
        float sqj = g_sq[m][j];
        float dd = sqi + sqj - 2.0f * dot;
        float d = sqrtf(fmaxf(dd, 0.0f) + EPS_C);
        if (m < 2) dsum += d; else demb = d;
    }

    float davg = 0.5f * dsum;
    float pw = 1.0f / (1.0f + expf(-RHO_C * (TAU_C - davg)));
    g_pw[i][j] = pw;
    g_tk[i][j] = make_float2(demb, 1.0f - pw);

    // deterministic block reduction of 256 pw values -> den partial
    float v = pw;
    #pragma unroll
    for (int o = 16; o > 0; o >>= 1) v += __shfl_down_sync(0xffffffffu, v, o);
    __shared__ float swp[8];
    int lane = t & 31, warp = t >> 5;
    if (lane == 0) swp[warp] = v;
    __syncthreads();
    if (warp == 0) {
        float w = (lane < 8) ? swp[lane] : 0.0f;
        #pragma unroll
        for (int o = 4; o > 0; o >>= 1) w += __shfl_down_sync(0xffffffffu, w, o);
        if (lane == 0) g_partden[blockIdx.y * 20 + blockIdx.x] = w;
    }
}

// ---------------- kernel 3: O(N^3) triplet pass + fused final ----------------
// grid: N blocks (one per i), 160 threads (each thread owns j and j+160)
__global__ void __launch_bounds__(160) k_triplet(float* __restrict__ out) {
    int i = blockIdx.x;
    int t = threadIdx.x;          // 0..159

    __shared__ float2 s[N];       // (d_emb[i][k], 1 - pw[i][k])
    s[t]       = g_tk[i][t];
    s[t + 160] = g_tk[i][t + 160];
    __syncthreads();

    int j0 = t, j1 = t + 160;
    float dij0 = s[j0].x, dij1 = s[j1].x;
    float pw0 = g_pw[i][j0], pw1 = g_pw[i][j1];

    float maxs0 = 0.0f, maxs1 = 0.0f;   // pos_semihard (values >= 0)
    float minn0 = 1e30f, minn1 = 1e30f; // norm_l

    #pragma unroll 4
    for (int k = 0; k < N; k++) {
        float2 v = s[k];                // LDS.64 uniform broadcast
        float dk = v.x, bk = v.y;
        // Match reference association: diff = d[i,k] - d[i,j];
        // tl = relu(MARGIN - diff). k==j gives tl == 0.2f EXACTLY (semihard).
        {
            float diff = dk - dij0;
            float tl = fmaxf(MARGIN_C - diff, 0.0f);
            float w  = pw0 * bk;
            bool p   = (tl <= MARGIN_C);          // semihard iff p (tl==0 -> vs==0)
            float vs = p ? tl * w : 0.0f;
            maxs0 = fmaxf(maxs0, vs);
            float vh = p ? tl : fmaf(-RHO_C, w, tl);
            minn0 = fminf(minn0, vh);
        }
        {
            float diff = dk - dij1;
            float tl = fmaxf(MARGIN_C - diff, 0.0f);
            float w  = pw1 * bk;
            bool p   = (tl <= MARGIN_C);
            float vs = p ? tl * w : 0.0f;
            maxs1 = fmaxf(maxs1, vs);
            float vh = p ? tl : fmaf(-RHO_C, w, tl);
            minn1 = fminf(minn1, vh);
        }
    }

    float ph0 = (minn0 < 0.0f) ? (minn0 + RHO_C) : 0.0f;
    float ph1 = (minn1 < 0.0f) ? (minn1 + RHO_C) : 0.0f;
    float pos0 = maxs0 + ((maxs0 <= SEMIHARD_THRESH_C) ? ph0 : 0.0f);
    float pos1 = maxs1 + ((maxs1 <= SEMIHARD_THRESH_C) ? ph1 : 0.0f);
    float contrib = pos0 * pw0 + pos1 * pw1;

    // deterministic block reduction of 160 values (5 warps)
    float v = contrib;
    #pragma unroll
    for (int o = 16; o > 0; o >>= 1) v += __shfl_down_sync(0xffffffffu, v, o);
    __shared__ float swp[5];
    int lane = t & 31, warp = t >> 5;
    if (lane == 0) swp[warp] = v;
    __syncthreads();
    if (warp == 0 && lane == 0) {
        float w = swp[0] + swp[1] + swp[2] + swp[3] + swp[4];
        g_partnum[i] = w;
    }

    // ---- fused final: last block to finish sums everything ----
    __threadfence();
    __shared__ bool is_last;
    if (t == 0) {
        unsigned tk = atomicAdd(&g_counter, 1u);
        is_last = (tk == (unsigned)(gridDim.x - 1));
    }
    __syncthreads();
    if (!is_last) return;

    float num = 0.0f, den = 0.0f;
    for (int b = t; b < N; b += 160)   num += __ldcg(&g_partnum[b]);
    for (int b = t; b < 400; b += 160) den += __ldcg(&g_partden[b]);
    #pragma unroll
    for (int o = 16; o > 0; o >>= 1) {
        num += __shfl_down_sync(0xffffffffu, num, o);
        den += __shfl_down_sync(0xffffffffu, den, o);
    }
    __shared__ float sn[5], sd2[5];
    if (lane == 0) { sn[warp] = num; sd2[warp] = den; }
    __syncthreads();
    if (t == 0) {
        float fn = sn[0] + sn[1] + sn[2] + sn[3] + sn[4];
        float fd = sd2[0] + sd2[1] + sd2[2] + sd2[3] + sd2[4];
        out[0] = (fd > 0.0f) ? (fn / fmaxf(fd, EPS_C)) : 0.0f;
    }
}

extern "C" void kernel_launch(void* const* d_in, const int* in_sizes, int n_in,
                              void* d_out, int out_size) {
    (void)n_in; (void)out_size;
    const float* src = (const float*)d_in[0];
    const float* emb = (const float*)d_in[1];
    if (n_in >= 2 && in_sizes[0] == N * D && in_sizes[1] == 2 * N * D) {
        const float* tmp = src; src = emb; emb = tmp;
    }
    float* out = (float*)d_out;

    k_normalize<<<NMAT * N, 128>>>(src, emb);
    k_distpw<<<dim3(20, 20), 256>>>();
    k_triplet<<<N, 160>>>(out);
}

// round 5
// speedup vs baseline: 1.6556x; 1.1827x over previous
#include <cuda_runtime.h>
#include <math.h>

#define N 320
#define D 128
#define NMAT 3            // src0, src1, emb
#define RHO_C 10.0f
#define MARGIN_C 0.2f
#define TAU_C 1.3f
#define SEMIHARD_THRESH_C 0.01f
#define EPS_C 1e-12f

// ---------------- device scratch (no allocations allowed) ----------------
__device__ float  g_rinv[NMAT][N];      // 1 / max(||x_r||, eps)
__device__ float  g_sq[NMAT][N];        // ||a_r||^2 of normalized row = s2*(rn*rn)
__device__ float  g_pw[N][N];           // pair weights
__device__ float2 g_tk[N][N];           // (d_emb[i][k], 1 - pw[i][k])
__device__ float  g_partden[400];       // per-block partial sums of pair_w
__device__ float  g_partnum[N];         // per-i partial sums of pos*pair_w
__device__ unsigned int g_counter;      // last-block ticket for fused final

// ---------------- kernel 1: per-row inverse norms (warp per row) ------------
// 960 rows -> 120 blocks x 256 threads (8 warps/block), no __syncthreads
__global__ void __launch_bounds__(256) k_rownorm(const float* __restrict__ src,
                                                 const float* __restrict__ emb) {
    if (blockIdx.x == 0 && threadIdx.x == 0) g_counter = 0;  // reset ticket each launch
    int gw = (blockIdx.x * 256 + threadIdx.x) >> 5;          // global warp id
    int lane = threadIdx.x & 31;
    if (gw >= NMAT * N) return;
    int m = gw / N, r = gw % N;
    const float* p = (m < 2) ? (src + ((size_t)m * N + r) * D) : (emb + (size_t)r * D);
    float4 x = ((const float4*)p)[lane];
    float s = x.x * x.x + x.y * x.y + x.z * x.z + x.w * x.w;
    #pragma unroll
    for (int o = 16; o > 0; o >>= 1) s += __shfl_xor_sync(0xffffffffu, s, o);
    float rn = 1.0f / fmaxf(sqrtf(s), EPS_C);
    if (lane == 0) {
        g_rinv[m][r] = rn;
        g_sq[m][r]   = s * (rn * rn);   // association matters: matches dot*(ri*rj) on diagonal
    }
}

// ---------------- kernel 2: fused distances + pair weights + den partials ---
// grid: (20, 20), 256 threads; each block owns a 16x16 (i,j) tile, loops m.
// Reads RAW inputs; d^2 = sq_i + sq_j - 2*dot_raw*(rinv_i*rinv_j).
#define PADW 132   // 128 + 4 floats pad; keeps float4 alignment, tames conflicts
__global__ void __launch_bounds__(256) k_distpw(const float* __restrict__ src,
                                                const float* __restrict__ emb) {
    int i0 = blockIdx.y * 16;
    int j0 = blockIdx.x * 16;
    __shared__ float Ai[16][PADW];
    __shared__ float Aj[16][PADW];

    int t  = threadIdx.x;
    int tx = t & 15, ty = t >> 4;
    int i = i0 + ty, j = j0 + tx;

    float dsum = 0.0f;
    float demb = 0.0f;

    #pragma unroll 1
    for (int m = 0; m < NMAT; m++) {
        __syncthreads();   // protect previous iteration's reads
        const float* base = (m < 2) ? (src + (size_t)m * N * D) : emb;
        // vectorized tile load: 16 rows x 32 float4 per side, 2 per thread/side
        for (int e = t; e < 16 * 32; e += 256) {
            int r = e >> 5, c4 = e & 31;
            const float4* gi = (const float4*)(base + (size_t)(i0 + r) * D);
            const float4* gj = (const float4*)(base + (size_t)(j0 + r) * D);
            *(float4*)&Ai[r][c4 * 4] = gi[c4];
            *(float4*)&Aj[r][c4 * 4] = gj[c4];
        }
        __syncthreads();

        const float4* ai = (const float4*)&Ai[ty][0];
        const float4* aj = (const float4*)&Aj[tx][0];
        float d0 = 0.f, d1 = 0.f, d2a = 0.f, d3 = 0.f;
        #pragma unroll 8
        for (int c = 0; c < 32; c++) {
            float4 a = ai[c];
            float4 b = aj[c];
            d0  += a.x * b.x;
            d1  += a.y * b.y;
            d2a += a.z * b.z;
            d3  += a.w * b.w;
        }
        float dot = (d0 + d1) + (d2a + d3);
        float sqi = g_sq[m][i];
        float sqj = g_sq[m][j];
        float rij = g_rinv[m][i] * g_rinv[m][j];
        float dd = sqi + sqj - 2.0f * (dot * rij);   // diagonal: dot*rij == sqi bitwise
        float d = sqrtf(fmaxf(dd, 0.0f) + EPS_C);
        if (m < 2) dsum += d; else demb = d;
    }

    float davg = 0.5f * dsum;
    float pw = 1.0f / (1.0f + expf(-RHO_C * (TAU_C - davg)));
    g_pw[i][j] = pw;
    g_tk[i][j] = make_float2(demb, 1.0f - pw);

    // deterministic block reduction of 256 pw values -> den partial
    float v = pw;
    #pragma unroll
    for (int o = 16; o > 0; o >>= 1) v += __shfl_down_sync(0xffffffffu, v, o);
    __shared__ float swp[8];
    int lane = t & 31, warp = t >> 5;
    if (lane == 0) swp[warp] = v;
    __syncthreads();
    if (warp == 0) {
        float w = (lane < 8) ? swp[lane] : 0.0f;
        #pragma unroll
        for (int o = 4; o > 0; o >>= 1) w += __shfl_down_sync(0xffffffffu, w, o);
        if (lane == 0) g_partden[blockIdx.y * 20 + blockIdx.x] = w;
    }
}

// ---------------- kernel 3: O(N^3) triplet pass + fused final ----------------
// grid: N blocks (one per i), 160 threads (each thread owns j and j+160)
__global__ void __launch_bounds__(160) k_triplet(float* __restrict__ out) {
    int i = blockIdx.x;
    int t = threadIdx.x;          // 0..159

    __shared__ float2 s[N];       // (d_emb[i][k], 1 - pw[i][k])
    s[t]       = g_tk[i][t];
    s[t + 160] = g_tk[i][t + 160];
    __syncthreads();

    float dij0 = s[t].x,       dij1 = s[t + 160].x;
    float pw0  = g_pw[i][t],   pw1  = g_pw[i][t + 160];

    float maxs0 = 0.0f, maxs1 = 0.0f;   // pos_semihard (values >= 0)
    float minn0 = 1e30f, minn1 = 1e30f; // min over HARD entries only (equivalent:
                                        // non-hard entries are >=0; pos_hard clips at 0)

    #pragma unroll 8
    for (int k = 0; k < N; k++) {
        float2 v = s[k];                // LDS.64 uniform broadcast
        float dk = v.x, bk = v.y;
        // Match reference association: diff = d[i,k] - d[i,j];
        // tl = relu(MARGIN - diff). k==j gives tl == 0.2f EXACTLY (semihard).
        {
            float diff = dk - dij0;
            float tl = fmaxf(MARGIN_C - diff, 0.0f);
            float w  = pw0 * bk;
            float tlw = tl * w;
            if (tl <= MARGIN_C) maxs0 = fmaxf(maxs0, tlw);
            else                minn0 = fminf(minn0, fmaf(-RHO_C, w, tl));
        }
        {
            float diff = dk - dij1;
            float tl = fmaxf(MARGIN_C - diff, 0.0f);
            float w  = pw1 * bk;
            float tlw = tl * w;
            if (tl <= MARGIN_C) maxs1 = fmaxf(maxs1, tlw);
            else                minn1 = fminf(minn1, fmaf(-RHO_C, w, tl));
        }
    }

    float ph0 = (minn0 < 0.0f) ? (minn0 + RHO_C) : 0.0f;
    float ph1 = (minn1 < 0.0f) ? (minn1 + RHO_C) : 0.0f;
    float pos0 = maxs0 + ((maxs0 <= SEMIHARD_THRESH_C) ? ph0 : 0.0f);
    float pos1 = maxs1 + ((maxs1 <= SEMIHARD_THRESH_C) ? ph1 : 0.0f);
    float contrib = pos0 * pw0 + pos1 * pw1;

    // deterministic block reduction of 160 values (5 warps)
    float v = contrib;
    #pragma unroll
    for (int o = 16; o > 0; o >>= 1) v += __shfl_down_sync(0xffffffffu, v, o);
    __shared__ float swp[5];
    int lane = t & 31, warp = t >> 5;
    if (lane == 0) swp[warp] = v;
    __syncthreads();
    if (warp == 0 && lane == 0) {
        g_partnum[i] = swp[0] + swp[1] + swp[2] + swp[3] + swp[4];
    }

    // ---- fused final: last block to finish sums everything ----
    __threadfence();
    __shared__ bool is_last;
    if (t == 0) {
        unsigned tk = atomicAdd(&g_counter, 1u);
        is_last = (tk == (unsigned)(gridDim.x - 1));
    }
    __syncthreads();
    if (!is_last) return;

    float num = 0.0f, den = 0.0f;
    for (int b = t; b < N; b += 160)   num += __ldcg(&g_partnum[b]);
    for (int b = t; b < 400; b += 160) den += __ldcg(&g_partden[b]);
    #pragma unroll
    for (int o = 16; o > 0; o >>= 1) {
        num += __shfl_down_sync(0xffffffffu, num, o);
        den += __shfl_down_sync(0xffffffffu, den, o);
    }
    __shared__ float sn[5], sd2[5];
    if (lane == 0) { sn[warp] = num; sd2[warp] = den; }
    __syncthreads();
    if (t == 0) {
        float fn = sn[0] + sn[1] + sn[2] + sn[3] + sn[4];
        float fd = sd2[0] + sd2[1] + sd2[2] + sd2[3] + sd2[4];
        out[0] = (fd > 0.0f) ? (fn / fmaxf(fd, EPS_C)) : 0.0f;
    }
}

extern "C" void kernel_launch(void* const* d_in, const int* in_sizes, int n_in,
                              void* d_out, int out_size) {
    (void)n_in; (void)out_size;
    const float* src = (const float*)d_in[0];
    const float* emb = (const float*)d_in[1];
    if (n_in >= 2 && in_sizes[0] == N * D && in_sizes[1] == 2 * N * D) {
        const float* tmp = src; src = emb; emb = tmp;
    }
    float* out = (float*)d_out;

    k_rownorm<<<(NMAT * N * 32 + 255) / 256, 256>>>(src, emb);
    k_distpw<<<dim3(20, 20), 256>>>(src, emb);
    k_triplet<<<N, 160>>>(out);
}

// round 6
// speedup vs baseline: 1.7607x; 1.0635x over previous
#include <cuda_runtime.h>
#include <math.h>

#define N 320
#define D 128
#define NMAT 3
#define RHO_C 10.0f
#define MARGIN_C 0.2f
#define TAU_C 1.3f
#define SEMIHARD_THRESH_C 0.01f
#define EPS_C 1e-12f
#define NTILE 20                 // N/16
#define NTRI  210                // 20*21/2 lower-triangle tiles

// ---------------- device scratch (no allocations allowed) ----------------
__device__ float4 g_tk4[N][N];       // (d_emb[i][k], bk=1-pw, RHO*bk, pw)
__device__ float  g_partden[NTRI];   // per-tile pw sums (x2 for off-diag)
__device__ float  g_partnum[N];      // per-i partial sums of pos*pair_w
__device__ unsigned int g_counter;   // last-block ticket for fused final

// ---------------- kernel 1: fused norms + distances + pair weights ----------
// 210 lower-triangle 16x16 tiles, 256 threads. Mirrors results to (j,i).
#define PADW 132
__global__ void __launch_bounds__(256) k_distpw(const float* __restrict__ src,
                                                const float* __restrict__ emb) {
    // decode lower-triangle tile (bi >= bj)
    int b = blockIdx.x;
    int bi = (int)((sqrtf(8.0f * (float)b + 1.0f) - 1.0f) * 0.5f);
    while ((bi + 1) * (bi + 2) / 2 <= b) bi++;
    while (bi * (bi + 1) / 2 > b) bi--;
    int bj = b - bi * (bi + 1) / 2;
    int i0 = bi * 16, j0 = bj * 16;

    __shared__ float Ai[16][PADW];
    __shared__ float Aj[16][PADW];
    __shared__ float s_sq[32];   // [0..15]=i rows, [16..31]=j rows
    __shared__ float s_ri[32];

    int t  = threadIdx.x;
    int tx = t & 15, ty = t >> 4;
    int lane = t & 31, warp = t >> 5;
    int i = i0 + ty, j = j0 + tx;

    if (b == 0 && t == 0) g_counter = 0;   // reset ticket (precedes k_triplet)

    float dsum = 0.0f, demb = 0.0f;

    #pragma unroll 1
    for (int m = 0; m < NMAT; m++) {
        __syncthreads();  // protect previous iteration's smem reads
        const float* base = (m < 2) ? (src + (size_t)m * N * D) : emb;
        for (int e = t; e < 16 * 32; e += 256) {
            int r = e >> 5, c4 = e & 31;
            *(float4*)&Ai[r][c4 * 4] = ((const float4*)(base + (size_t)(i0 + r) * D))[c4];
            *(float4*)&Aj[r][c4 * 4] = ((const float4*)(base + (size_t)(j0 + r) * D))[c4];
        }
        __syncthreads();

        // warp-cooperative row norms: warp w handles rows 4w..4w+3 of 32
        #pragma unroll
        for (int rr = 0; rr < 4; rr++) {
            int row = warp * 4 + rr;
            const float* rp = (row < 16) ? &Ai[row][0] : &Aj[row - 16][0];
            float4 x = ((const float4*)rp)[lane];
            float ssum = x.x * x.x + x.y * x.y + x.z * x.z + x.w * x.w;
            #pragma unroll
            for (int o = 16; o > 0; o >>= 1) ssum += __shfl_xor_sync(0xffffffffu, ssum, o);
            if (lane == 0) {
                float rn = 1.0f / fmaxf(sqrtf(ssum), EPS_C);
                s_sq[row] = ssum * (rn * rn);
                s_ri[row] = rn;
            }
        }
        __syncthreads();

        const float4* ai = (const float4*)&Ai[ty][0];
        const float4* aj = (const float4*)&Aj[tx][0];
        float d0 = 0.f, d1 = 0.f, d2a = 0.f, d3 = 0.f;
        #pragma unroll 8
        for (int c = 0; c < 32; c++) {
            float4 a = ai[c];
            float4 bb = aj[c];
            d0  += a.x * bb.x;
            d1  += a.y * bb.y;
            d2a += a.z * bb.z;
            d3  += a.w * bb.w;
        }
        float dot = (d0 + d1) + (d2a + d3);
        float rij = s_ri[ty] * s_ri[16 + tx];
        float dd  = s_sq[ty] + s_sq[16 + tx] - 2.0f * (dot * rij);
        float d   = sqrtf(fmaxf(dd, 0.0f) + EPS_C);
        if (m < 2) dsum += d; else demb = d;
    }

    float davg = 0.5f * dsum;
    float pw = 1.0f / (1.0f + expf(-RHO_C * (TAU_C - davg)));
    float bk = 1.0f - pw;
    float4 rec = make_float4(demb, bk, RHO_C * bk, pw);
    g_tk4[i][j] = rec;
    if (bi != bj) g_tk4[j][i] = rec;   // bitwise symmetric by construction

    // deterministic block reduction of tile pw -> den partial (x2 off-diag)
    float v = pw;
    #pragma unroll
    for (int o = 16; o > 0; o >>= 1) v += __shfl_down_sync(0xffffffffu, v, o);
    __shared__ float swp[8];
    if (lane == 0) swp[warp] = v;
    __syncthreads();
    if (warp == 0) {
        float w = (lane < 8) ? swp[lane] : 0.0f;
        #pragma unroll
        for (int o = 4; o > 0; o >>= 1) w += __shfl_down_sync(0xffffffffu, w, o);
        if (lane == 0) g_partden[b] = (bi != bj) ? 2.0f * w : w;
    }
}

// ---------------- kernel 2: O(N^3) triplet pass + fused final ----------------
// grid: N blocks (one per i), 160 threads (each thread owns j and j+160)
__global__ void __launch_bounds__(160) k_triplet(float* __restrict__ out) {
    int i = blockIdx.x;
    int t = threadIdx.x;

    __shared__ float4 s4[N];   // (dk, bk, rbk, pw)
    s4[t]       = g_tk4[i][t];
    s4[t + 160] = g_tk4[i][t + 160];
    __syncthreads();

    float4 r0 = s4[t], r1 = s4[t + 160];
    float ndij0 = -r0.x, ndij1 = -r1.x;
    float pw0 = r0.w,    pw1 = r1.w;
    float npw0 = -pw0,   npw1 = -pw1;

    float maxs0 = 0.0f, maxs1 = 0.0f;     // max of m*bk over semihard (pwij factored out)
    float minn0 = 1e30f, minn1 = 1e30f;   // min over HARD entries of m - rbk*pw

    #pragma unroll 8
    for (int k = 0; k < N; k++) {
        float4 v = s4[k];                 // LDS.128 uniform broadcast
        float dk = v.x, bk = v.y, rbk = v.z;
        // diff = d[i,k] - d[i,j] (bitwise: dk + (-dij)); m = MARGIN - diff.
        // k==j -> diff==0 exactly -> m==0.2f exactly -> semihard. Do not refactor.
        {
            float diff = dk + ndij0;
            float m = MARGIN_C - diff;
            float vs = m * bk;            // m<=0 -> vs<=0, harmless vs maxs>=0
            if (m <= MARGIN_C) maxs0 = fmaxf(maxs0, vs);
            else               minn0 = fminf(minn0, fmaf(rbk, npw0, m));
        }
        {
            float diff = dk + ndij1;
            float m = MARGIN_C - diff;
            float vs = m * bk;
            if (m <= MARGIN_C) maxs1 = fmaxf(maxs1, vs);
            else               minn1 = fminf(minn1, fmaf(rbk, npw1, m));
        }
    }

    float psh0 = pw0 * maxs0, psh1 = pw1 * maxs1;       // pos_semihard
    float ph0 = (minn0 < 0.0f) ? (minn0 + RHO_C) : 0.0f;
    float ph1 = (minn1 < 0.0f) ? (minn1 + RHO_C) : 0.0f;
    float pos0 = psh0 + ((psh0 <= SEMIHARD_THRESH_C) ? ph0 : 0.0f);
    float pos1 = psh1 + ((psh1 <= SEMIHARD_THRESH_C) ? ph1 : 0.0f);
    float contrib = pos0 * pw0 + pos1 * pw1;

    // deterministic block reduction (5 warps)
    float v = contrib;
    #pragma unroll
    for (int o = 16; o > 0; o >>= 1) v += __shfl_down_sync(0xffffffffu, v, o);
    __shared__ float swp[5];
    int lane = t & 31, warp = t >> 5;
    if (lane == 0) swp[warp] = v;
    __syncthreads();
    if (warp == 0 && lane == 0)
        g_partnum[i] = swp[0] + swp[1] + swp[2] + swp[3] + swp[4];

    // ---- fused final: last block sums everything ----
    __threadfence();
    __shared__ bool is_last;
    if (t == 0) {
        unsigned tk = atomicAdd(&g_counter, 1u);
        is_last = (tk == (unsigned)(gridDim.x - 1));
    }
    __syncthreads();
    if (!is_last) return;

    float num = 0.0f, den = 0.0f;
    for (int b2 = t; b2 < N;    b2 += 160) num += __ldcg(&g_partnum[b2]);
    for (int b2 = t; b2 < NTRI; b2 += 160) den += __ldcg(&g_partden[b2]);
    #pragma unroll
    for (int o = 16; o > 0; o >>= 1) {
        num += __shfl_down_sync(0xffffffffu, num, o);
        den += __shfl_down_sync(0xffffffffu, den, o);
    }
    __shared__ float sn[5], sd2[5];
    if (lane == 0) { sn[warp] = num; sd2[warp] = den; }
    __syncthreads();
    if (t == 0) {
        float fn = sn[0] + sn[1] + sn[2] + sn[3] + sn[4];
        float fd = sd2[0] + sd2[1] + sd2[2] + sd2[3] + sd2[4];
        out[0] = (fd > 0.0f) ? (fn / fmaxf(fd, EPS_C)) : 0.0f;
    }
}

extern "C" void kernel_launch(void* const* d_in, const int* in_sizes, int n_in,
                              void* d_out, int out_size) {
    (void)n_in; (void)out_size;
    const float* src = (const float*)d_in[0];
    const float* emb = (const float*)d_in[1];
    if (n_in >= 2 && in_sizes[0] == N * D && in_sizes[1] == 2 * N * D) {
        const float* tmp = src; src = emb; emb = tmp;
    }
    float* out = (float*)d_out;

    k_distpw<<<NTRI, 256>>>(src, emb);
    k_triplet<<<N, 160>>>(out);
}